// round 8
// baseline (speedup 1.0000x reference)
#include <cuda_runtime.h>
#include <cuda_fp16.h>
#include <cstdint>
#include <math.h>

#define Bsz 4096
#define Ff  1024
#define Ee  16
#define Dd  8
#define Tt  1040
#define Ll  3
#define K1P 1088   // padded K for layer 1 (multiple of 64)

// ---------------- scratch (device globals; no allocation allowed) ----------
__device__ __align__(128) __half g_xc [Bsz*K1P];
__device__ __align__(128) __half g_ch1[Bsz*512];
__device__ __align__(128) __half g_ch2[Bsz*256];
__device__ __align__(128) __half g_hc [Bsz*128];
__device__ __align__(128) __half g_dg1[Bsz*512];
__device__ __align__(128) __half g_dg2[Bsz*256];
__device__ __align__(128) __half g_hd [Bsz*128];
// half weights, [K(pad), N] k-major (same layout as inputs, converted once)
__device__ __align__(128) __half g_wh1c[K1P*512];
__device__ __align__(128) __half g_wh1d[Dd*K1P*512];
__device__ __align__(128) __half g_wh2c[512*256];
__device__ __align__(128) __half g_wh2d[Dd*512*256];
__device__ __align__(128) __half g_wh3c[256*128];
__device__ __align__(128) __half g_wh3d[Dd*256*128];
__device__ float g_aux[Bsz];
__device__ int   g_cnt[Dd];
__device__ int   g_off[Dd];
__device__ int   g_perm[Bsz];

// ---------------- PTX helpers ----------------------------------------------
__device__ __forceinline__ uint32_t smem_u32(const void* p) {
    uint32_t a;
    asm("{ .reg .u64 t; cvta.to.shared.u64 t, %1; cvt.u32.u64 %0, t; }" : "=r"(a) : "l"(p));
    return a;
}
__device__ __forceinline__ void ldsm4(uint32_t* r, uint32_t addr) {
    asm volatile("ldmatrix.sync.aligned.m8n8.x4.shared.b16 {%0,%1,%2,%3}, [%4];"
        : "=r"(r[0]), "=r"(r[1]), "=r"(r[2]), "=r"(r[3]) : "r"(addr));
}
__device__ __forceinline__ void ldsm4t(uint32_t* r, uint32_t addr) {
    asm volatile("ldmatrix.sync.aligned.m8n8.x4.trans.shared.b16 {%0,%1,%2,%3}, [%4];"
        : "=r"(r[0]), "=r"(r[1]), "=r"(r[2]), "=r"(r[3]) : "r"(addr));
}
__device__ __forceinline__ void mma_f16(float* c, const uint32_t* a, const uint32_t* b) {
    asm volatile("mma.sync.aligned.m16n8k16.row.col.f32.f16.f16.f32 "
        "{%0,%1,%2,%3}, {%4,%5,%6,%7}, {%8,%9}, {%0,%1,%2,%3};"
        : "+f"(c[0]), "+f"(c[1]), "+f"(c[2]), "+f"(c[3])
        : "r"(a[0]), "r"(a[1]), "r"(a[2]), "r"(a[3]), "r"(b[0]), "r"(b[1]));
}
__device__ __forceinline__ void cpa16(uint32_t dst, const void* src) {
    asm volatile("cp.async.cg.shared.global [%0], [%1], 16;" :: "r"(dst), "l"(src) : "memory");
}
#define CPA_COMMIT() asm volatile("cp.async.commit_group;" ::: "memory")
#define CPA_WAIT1()  asm volatile("cp.async.wait_group 1;" ::: "memory")

// ---------------- block reduce ----------------------------------------------
__device__ __forceinline__ float blockReduceSum256(float v, float* red) {
    int tid = threadIdx.x;
    #pragma unroll
    for (int o = 16; o; o >>= 1) v += __shfl_down_sync(0xffffffffu, v, o);
    if ((tid & 31) == 0) red[tid >> 5] = v;
    __syncthreads();
    if (tid < 32) {
        float x = (tid < 8) ? red[tid] : 0.f;
        #pragma unroll
        for (int o = 4; o; o >>= 1) x += __shfl_down_sync(0xffffffffu, x, o);
        if (tid == 0) red[0] = x;
    }
    __syncthreads();
    float r = red[0];
    __syncthreads();
    return r;
}

// ---------------- k_cvt: convert ALL weights fp32->half (pad layer1 K) ------
#define CVT_TOTAL 6488064
#define CVT_BLOCKS 3168        // 3168*256*8 == CVT_TOTAL

__global__ void k_cvt(const float* __restrict__ cW1, const float* __restrict__ dW1,
                      const float* __restrict__ cW2, const float* __restrict__ dW2,
                      const float* __restrict__ cW3, const float* __restrict__ dW3)
{
    size_t idx = ((size_t)blockIdx.x * 256 + threadIdx.x) * 8;
    const float* src; __half* dst;
    int KIN, KPAD, N;
    size_t off;
    if      (idx < 557056)  { src = cW1; dst = g_wh1c; KIN = Tt;  KPAD = K1P; N = 512; off = idx; }
    else if (idx < 5013504) { src = dW1; dst = g_wh1d; KIN = Tt;  KPAD = K1P; N = 512; off = idx - 557056; }
    else if (idx < 5144576) { src = cW2; dst = g_wh2c; KIN = 512; KPAD = 512; N = 256; off = idx - 5013504; }
    else if (idx < 6193152) { src = dW2; dst = g_wh2d; KIN = 512; KPAD = 512; N = 256; off = idx - 5144576; }
    else if (idx < 6225920) { src = cW3; dst = g_wh3c; KIN = 256; KPAD = 256; N = 128; off = idx - 6193152; }
    else                    { src = dW3; dst = g_wh3d; KIN = 256; KPAD = 256; N = 128; off = idx - 6225920; }

    size_t per = (size_t)KPAD * N;
    int d = (int)(off / per);
    size_t r = off % per;
    int k = (int)(r / N), n = (int)(r % N);
    uint4 u;
    if (k < KIN) {
        const float* s = src + ((size_t)d * KIN + k) * N + n;
        float4 f0 = *(const float4*)s;
        float4 f1 = *(const float4*)(s + 4);
        __half2 h0 = __floats2half2_rn(f0.x, f0.y), h1 = __floats2half2_rn(f0.z, f0.w);
        __half2 h2 = __floats2half2_rn(f1.x, f1.y), h3 = __floats2half2_rn(f1.z, f1.w);
        u.x = *(uint32_t*)&h0; u.y = *(uint32_t*)&h1;
        u.z = *(uint32_t*)&h2; u.w = *(uint32_t*)&h3;
    } else {
        u = make_uint4(0, 0, 0, 0);
    }
    *(uint4*)(dst + off) = u;
}

// ---------------- partition: counts, offsets, permutation (one block) -------
__global__ void k_part(const int* __restrict__ dom) {
    __shared__ int scnt[Dd], soff[Dd], scur[Dd];
    int t = threadIdx.x;
    if (t < Dd) { scnt[t] = 0; scur[t] = 0; }
    __syncthreads();
    int dv[4];
    #pragma unroll
    for (int i = 0; i < 4; i++) { dv[i] = dom[t + 1024 * i]; atomicAdd(&scnt[dv[i]], 1); }
    __syncthreads();
    if (t == 0) {
        int s = 0;
        for (int d = 0; d < Dd; d++) { soff[d] = s; g_off[d] = s; g_cnt[d] = scnt[d]; s += scnt[d]; }
    }
    __syncthreads();
    #pragma unroll
    for (int i = 0; i < 4; i++) {
        int p = atomicAdd(&scur[dv[i]], 1);
        g_perm[soff[dv[i]] + p] = t + 1024 * i;
    }
}

// ---------------- k_prep: LayerNorm + domain affine + cross net + aux -------
__global__ void k_prep(const float* __restrict__ x, const int* __restrict__ dom,
                       const float* __restrict__ pnw, const float* __restrict__ pnb,
                       const float* __restrict__ demb,
                       const float* __restrict__ cw, const float* __restrict__ cb,
                       const float* __restrict__ aW1, const float* __restrict__ ab1,
                       const float* __restrict__ aW2, const float* __restrict__ ab2)
{
    int r = blockIdx.x;
    int tid = threadIdx.x;
    __shared__ float s_x0[Tt];
    __shared__ float s_xc[Tt];
    __shared__ float red[32];

    const float* xr = x + (size_t)r * Ff;
    float sum = 0.f, sq = 0.f;
    for (int j = tid; j < Ff; j += 256) { float v = xr[j]; sum += v; sq += v * v; }
    float tot  = blockReduceSum256(sum, red);
    float tot2 = blockReduceSum256(sq, red);
    float mean = tot * (1.f / Ff);
    float var  = tot2 * (1.f / Ff) - mean * mean;
    float rstd = rsqrtf(var + 1e-5f);

    int d = dom[r];
    const float* wr = pnw + (size_t)d * Ff;
    const float* br = pnb + (size_t)d * Ff;
    for (int j = tid; j < Ff; j += 256) {
        float nv = (xr[j] - mean) * rstd * wr[j] + br[j];
        s_x0[j] = nv;
        s_xc[j] = nv;
    }
    for (int e = tid; e < Ee; e += 256) {
        float v = demb[d * Ee + e];
        s_x0[Ff + e] = v;
        s_xc[Ff + e] = v;
    }
    __syncthreads();

    for (int i = 0; i < Ll; i++) {
        const float* wi = cw + i * Tt;
        const float* bi = cb + i * Tt;
        float p = 0.f;
        for (int j = tid; j < Tt; j += 256) p += s_xc[j] * wi[j];
        float proj = blockReduceSum256(p, red);
        for (int j = tid; j < Tt; j += 256)
            s_xc[j] = fmaf(s_x0[j], proj, bi[j] + s_xc[j]);
        __syncthreads();
    }

    __half* out = g_xc + (size_t)r * K1P;
    for (int j = tid; j < Tt; j += 256) out[j] = __float2half_rn(s_xc[j]);
    if (tid < K1P - Tt) out[Tt + tid] = __float2half_rn(0.f);

    if (tid < 32) {
        float s = ab1[tid];
        #pragma unroll
        for (int e = 0; e < Ee; e++) s = fmaf(s_x0[Ff + e], aW1[e * 32 + tid], s);
        s = fmaxf(s, 0.f) * aW2[tid];
        #pragma unroll
        for (int o = 16; o; o >>= 1) s += __shfl_down_sync(0xffffffffu, s, o);
        if (tid == 0) g_aux[r] = s + ab2[0];
    }
}

// ---------------- fp16 tensor-core GEMM: 4 warps, 64x64 warp tiles ----------
// C[M,N](half) = act(A[M,K](half) @ W[K,N](half) + bias(fp32))
// 128 threads, CTA 128x128, BK=64, 3-stage cp.async, register-double-buffered
// fragments. z=0: center, z=1..8: domain nets.
#define BK     64
#define LDH    72                 // A smem row pitch (halfs)
#define LDB    136                // B smem row pitch (halfs)
#define ASZ    (128*LDH)          // halfs per A stage (9216)
#define BSZ    (BK*LDB)           // halfs per B stage (8704)
#define STAGES 3
#define DYNSM  (STAGES*(ASZ+BSZ)*2)   // 107520 bytes

template<int K, int N, bool RELU, int LAYER>
__global__ __launch_bounds__(128, 2)
void gemm_f16(const __half* __restrict__ Ac, const __half* __restrict__ Ad,
              const __half* __restrict__ Wc, const __half* __restrict__ Wd,
              const float* __restrict__ bc, const float* __restrict__ bd,
              __half* __restrict__ Cc, __half* __restrict__ Cd)
{
    extern __shared__ __align__(16) __half tiles[];
    __shared__ int rowA[128], rowC[128];

    const int z  = blockIdx.z;
    const int n0 = blockIdx.x * 128;
    const int m0 = blockIdx.y * 128;

    const __half *A, *W;
    const float* bias;
    __half* C;
    int cnt;
    if (z == 0) { A = Ac; W = Wc; bias = bc; C = Cc; cnt = Bsz; }
    else {
        int d = z - 1;
        cnt = g_cnt[d];
        if (m0 >= cnt) return;
        A = Ad; W = Wd + (size_t)d * K * N; bias = bd + d * N; C = Cd;
    }

    const int tid  = threadIdx.x;
    const int wid  = tid >> 5;
    const int lane = tid & 31;

    {
        int t = tid;
        if (z == 0) { rowA[t] = m0 + t; rowC[t] = m0 + t; }
        else {
            int off = g_off[z - 1];
            int mm  = min(m0 + t, cnt - 1);
            int slot = off + mm;
            if (LAYER == 1)      { rowA[t] = g_perm[slot]; rowC[t] = slot; }
            else if (LAYER == 2) { rowA[t] = slot;         rowC[t] = slot; }
            else                 { rowA[t] = slot;         rowC[t] = g_perm[slot]; }
        }
    }
    __syncthreads();

    // ---- loader mapping: 8 A slots + 8 B slots per thread, 16B each --------
    // A slot i: s = tid + 128*i -> row (tid>>3)+16i, kcol8 (tid&7)*8
    uint32_t aOff[8];             // element offsets into A (gathered rows)
    {
        int ar0 = tid >> 3, ac8 = (tid & 7) * 8;
        #pragma unroll
        for (int i = 0; i < 8; i++)
            aOff[i] = (uint32_t)rowA[ar0 + 16 * i] * K + ac8;
    }
    const uint32_t aDst0 = (uint32_t)((tid >> 3) * LDH + (tid & 7) * 8) * 2;
    // B slot i: krow (tid>>4)+8i, ncol8 (tid&15)*8
    const uint32_t bOff0 = (uint32_t)((tid >> 4) * N + n0 + (tid & 15) * 8);
    const uint32_t bDst0 = (uint32_t)((tid >> 4) * LDB + (tid & 15) * 8) * 2;

    const uint32_t sbase = smem_u32(tiles);

    // ---- fragment address components: warp grid 2x2, tile 64x64 ------------
    const int wm = (wid >> 1) * 64;
    const int wn = (wid & 1) * 64;
    const int gid = lane >> 2, tig = lane & 3;
    const uint32_t aRowOff = (uint32_t)((wm + (lane & 15)) * LDH + ((lane >> 4) * 8)) * 2;
    const uint32_t bAddrOff = (uint32_t)(((lane & 7) + ((lane >> 3) & 1) * 8) * LDB
                                         + wn + (lane >> 4) * 8) * 2;

    float acc[4][8][4];
    #pragma unroll
    for (int mt = 0; mt < 4; mt++)
        #pragma unroll
        for (int nt = 0; nt < 8; nt++)
            #pragma unroll
            for (int i = 0; i < 4; i++) acc[mt][nt][i] = 0.f;

    const int NCH = K / BK;

    auto issue = [&](int c, int st) {
        uint32_t aS = sbase + (uint32_t)(st * ASZ) * 2 + aDst0;
        uint32_t bS = sbase + (uint32_t)(STAGES * ASZ + st * BSZ) * 2 + bDst0;
        int k0 = c * BK;
        #pragma unroll
        for (int i = 0; i < 8; i++)
            cpa16(aS + i * (16 * LDH * 2), A + aOff[i] + k0);
        const __half* wp = W + (size_t)k0 * N + bOff0;
        #pragma unroll
        for (int i = 0; i < 8; i++)
            cpa16(bS + i * (8 * LDB * 2), wp + (size_t)i * 8 * N);
    };

    // prologue: chunks 0,1 -> stages 0,1
    issue(0, 0); CPA_COMMIT();
    issue(1, 1); CPA_COMMIT();

    uint32_t afr[2][4][4];
    uint32_t bfr[2][4][4];

    for (int c = 0; c < NCH; c++) {
        CPA_WAIT1();
        __syncthreads();
        if (c + 2 < NCH) issue(c + 2, (c + 2) % STAGES);
        CPA_COMMIT();

        const int st = c % STAGES;
        const uint32_t aB = sbase + (uint32_t)(st * ASZ) * 2;
        const uint32_t bB = sbase + (uint32_t)(STAGES * ASZ + st * BSZ) * 2;

        // load fragments for k-step 0
        #pragma unroll
        for (int mt = 0; mt < 4; mt++)
            ldsm4(afr[0][mt], aB + aRowOff + (uint32_t)(mt * 16 * LDH) * 2);
        #pragma unroll
        for (int ntp = 0; ntp < 4; ntp++)
            ldsm4t(bfr[0][ntp], bB + bAddrOff + (uint32_t)(ntp * 16) * 2);

        #pragma unroll
        for (int ks = 0; ks < BK / 16; ks++) {
            const int cb = ks & 1, nb = cb ^ 1;
            if (ks + 1 < BK / 16) {
                const int kk = (ks + 1) * 16;
                #pragma unroll
                for (int mt = 0; mt < 4; mt++)
                    ldsm4(afr[nb][mt], aB + aRowOff + (uint32_t)(mt * 16 * LDH + kk) * 2);
                #pragma unroll
                for (int ntp = 0; ntp < 4; ntp++)
                    ldsm4t(bfr[nb][ntp], bB + bAddrOff + (uint32_t)(kk * LDB + ntp * 16) * 2);
            }
            #pragma unroll
            for (int mt = 0; mt < 4; mt++)
                #pragma unroll
                for (int ntp = 0; ntp < 4; ntp++) {
                    mma_f16(acc[mt][ntp * 2 + 0], afr[cb][mt], bfr[cb][ntp] + 0);
                    mma_f16(acc[mt][ntp * 2 + 1], afr[cb][mt], bfr[cb][ntp] + 2);
                }
        }
    }
    __syncthreads();

    // epilogue: bias + act -> half, stage in smem, coalesced store
    __half* stage = tiles;      // 128 x 136 halfs = 34816 B < DYNSM
    #pragma unroll
    for (int mt = 0; mt < 4; mt++) {
        #pragma unroll
        for (int nt = 0; nt < 8; nt++) {
            int col = wn + nt * 8 + 2 * tig;
            float bx = bias[n0 + col], by = bias[n0 + col + 1];
            float v0 = acc[mt][nt][0] + bx, v1 = acc[mt][nt][1] + by;
            float v2 = acc[mt][nt][2] + bx, v3 = acc[mt][nt][3] + by;
            if (RELU) {
                v0 = fmaxf(v0, 0.f); v1 = fmaxf(v1, 0.f);
                v2 = fmaxf(v2, 0.f); v3 = fmaxf(v3, 0.f);
            }
            int r0 = wm + mt * 16 + gid;
            *(__half2*)&stage[r0 * 136 + col]       = __floats2half2_rn(v0, v1);
            *(__half2*)&stage[(r0 + 8) * 136 + col] = __floats2half2_rn(v2, v3);
        }
    }
    __syncthreads();
    #pragma unroll
    for (int i = 0; i < 16; i++) {
        int idx = tid + 128 * i;            // 0..2047
        int r = idx >> 4, c8 = (idx & 15) * 8;
        if (z == 0 || m0 + r < cnt) {
            uint4 v = *(uint4*)&stage[r * 136 + c8];
            *(uint4*)&C[(size_t)rowC[r] * N + n0 + c8] = v;
        }
    }
}

// ---------------- K_final: STAR fusion + final MLP + sigmoid ----------------
__global__ void k_final(const float* __restrict__ fW1, const float* __restrict__ fb1,
                        const float* __restrict__ fW2, const float* __restrict__ fb2,
                        float* __restrict__ out)
{
    int r = blockIdx.x;
    int t = threadIdx.x;
    __shared__ float fs[128];
    __shared__ float red[64];
    fs[t] = __half2float(g_hc[r * 128 + t]) * tanhf(__half2float(g_hd[r * 128 + t]));
    __syncthreads();
    if (t < 64) {
        float s = fb1[t];
        #pragma unroll
        for (int j = 0; j < 128; j++) s = fmaf(fs[j], fW1[j * 64 + t], s);
        red[t] = fmaxf(s, 0.f) * fW2[t];
    }
    __syncthreads();
    if (t < 32) {
        float v = red[t] + red[t + 32];
        #pragma unroll
        for (int o = 16; o; o >>= 1) v += __shfl_down_sync(0xffffffffu, v, o);
        if (t == 0) {
            float logit = v + fb2[0] + g_aux[r];
            out[r] = 1.f / (1.f + expf(-logit));
        }
    }
}

// ---------------- launch -----------------------------------------------------
extern "C" void kernel_launch(void* const* d_in, const int* in_sizes, int n_in,
                              void* d_out, int out_size)
{
    const float* x    = (const float*)d_in[0];
    const int*   dom  = (const int*)  d_in[1];
    const float* pnw  = (const float*)d_in[2];
    const float* pnb  = (const float*)d_in[3];
    const float* demb = (const float*)d_in[4];
    const float* cw   = (const float*)d_in[5];
    const float* cb   = (const float*)d_in[6];
    const float* cW1  = (const float*)d_in[7];
    const float* cb1  = (const float*)d_in[8];
    const float* cW2  = (const float*)d_in[9];
    const float* cb2  = (const float*)d_in[10];
    const float* cW3  = (const float*)d_in[11];
    const float* cb3  = (const float*)d_in[12];
    const float* dW1  = (const float*)d_in[13];
    const float* db1  = (const float*)d_in[14];
    const float* dW2  = (const float*)d_in[15];
    const float* db2  = (const float*)d_in[16];
    const float* dW3  = (const float*)d_in[17];
    const float* db3  = (const float*)d_in[18];
    const float* fW1  = (const float*)d_in[19];
    const float* fb1  = (const float*)d_in[20];
    const float* fW2  = (const float*)d_in[21];
    const float* fb2  = (const float*)d_in[22];
    const float* aW1  = (const float*)d_in[23];
    const float* ab1  = (const float*)d_in[24];
    const float* aW2  = (const float*)d_in[25];
    const float* ab2  = (const float*)d_in[26];
    float* out = (float*)d_out;

    __half *xcP, *ch1P, *ch2P, *hcP, *dg1P, *dg2P, *hdP;
    __half *wh1cP, *wh1dP, *wh2cP, *wh2dP, *wh3cP, *wh3dP;
    cudaGetSymbolAddress((void**)&xcP,  g_xc);
    cudaGetSymbolAddress((void**)&ch1P, g_ch1);
    cudaGetSymbolAddress((void**)&ch2P, g_ch2);
    cudaGetSymbolAddress((void**)&hcP,  g_hc);
    cudaGetSymbolAddress((void**)&dg1P, g_dg1);
    cudaGetSymbolAddress((void**)&dg2P, g_dg2);
    cudaGetSymbolAddress((void**)&hdP,  g_hd);
    cudaGetSymbolAddress((void**)&wh1cP, g_wh1c);
    cudaGetSymbolAddress((void**)&wh1dP, g_wh1d);
    cudaGetSymbolAddress((void**)&wh2cP, g_wh2c);
    cudaGetSymbolAddress((void**)&wh2dP, g_wh2d);
    cudaGetSymbolAddress((void**)&wh3cP, g_wh3c);
    cudaGetSymbolAddress((void**)&wh3dP, g_wh3d);

    cudaFuncSetAttribute(gemm_f16<K1P, 512, true,  1>, cudaFuncAttributeMaxDynamicSharedMemorySize, DYNSM);
    cudaFuncSetAttribute(gemm_f16<512, 256, true,  2>, cudaFuncAttributeMaxDynamicSharedMemorySize, DYNSM);
    cudaFuncSetAttribute(gemm_f16<256, 128, false, 3>, cudaFuncAttributeMaxDynamicSharedMemorySize, DYNSM);

    k_cvt<<<CVT_BLOCKS, 256>>>(cW1, dW1, cW2, dW2, cW3, dW3);
    k_part<<<1, 1024>>>(dom);
    k_prep<<<Bsz, 256>>>(x, dom, pnw, pnb, demb, cw, cb, aW1, ab1, aW2, ab2);

    // layer 1: K=1088(padded) -> N=512 ; z=0 center, z=1..8 domains
    gemm_f16<K1P, 512, true,  1><<<dim3(4, 32, 9), 128, DYNSM>>>(xcP,  xcP,  wh1cP, wh1dP, cb1, db1, ch1P, dg1P);
    // layer 2: K=512 -> N=256
    gemm_f16<512, 256, true,  2><<<dim3(2, 32, 9), 128, DYNSM>>>(ch1P, dg1P, wh2cP, wh2dP, cb2, db2, ch2P, dg2P);
    // layer 3: K=256 -> N=128
    gemm_f16<256, 128, false, 3><<<dim3(1, 32, 9), 128, DYNSM>>>(ch2P, dg2P, wh3cP, wh3dP, cb3, db3, hcP, hdP);

    k_final<<<Bsz, 128>>>(fW1, fb1, fW2, fb2, out);
}

// round 9
// speedup vs baseline: 1.1003x; 1.1003x over previous
#include <cuda_runtime.h>
#include <cuda_fp16.h>
#include <cstdint>
#include <math.h>

#define Bsz 4096
#define Ff  1024
#define Ee  16
#define Dd  8
#define Tt  1040
#define Ll  3
#define K1P 1088   // padded K for layer 1 (multiple of 64)

// ---------------- scratch (device globals; no allocation allowed) ----------
__device__ __align__(128) __half g_xc [Bsz*K1P];
__device__ __align__(128) __half g_ch1[Bsz*512];
__device__ __align__(128) __half g_hc [Bsz*128];
__device__ __align__(128) __half g_dg1[Bsz*512];
__device__ __align__(128) __half g_hd [Bsz*128];
// half weights, [K(pad), N] k-major (same layout as inputs, converted once)
__device__ __align__(128) __half g_wh1c[K1P*512];
__device__ __align__(128) __half g_wh1d[Dd*K1P*512];
__device__ __align__(128) __half g_wh2c[512*256];
__device__ __align__(128) __half g_wh2d[Dd*512*256];
__device__ __align__(128) __half g_wh3c[256*128];
__device__ __align__(128) __half g_wh3d[Dd*256*128];
__device__ float g_aux[Bsz];
__device__ int   g_cnt[Dd];
__device__ int   g_off[Dd];
__device__ int   g_perm[Bsz];

// ---------------- PTX helpers ----------------------------------------------
__device__ __forceinline__ uint32_t smem_u32(const void* p) {
    uint32_t a;
    asm("{ .reg .u64 t; cvta.to.shared.u64 t, %1; cvt.u32.u64 %0, t; }" : "=r"(a) : "l"(p));
    return a;
}
__device__ __forceinline__ void ldsm4(uint32_t* r, uint32_t addr) {
    asm volatile("ldmatrix.sync.aligned.m8n8.x4.shared.b16 {%0,%1,%2,%3}, [%4];"
        : "=r"(r[0]), "=r"(r[1]), "=r"(r[2]), "=r"(r[3]) : "r"(addr));
}
__device__ __forceinline__ void ldsm4t(uint32_t* r, uint32_t addr) {
    asm volatile("ldmatrix.sync.aligned.m8n8.x4.trans.shared.b16 {%0,%1,%2,%3}, [%4];"
        : "=r"(r[0]), "=r"(r[1]), "=r"(r[2]), "=r"(r[3]) : "r"(addr));
}
__device__ __forceinline__ void mma_f16(float* c, const uint32_t* a, const uint32_t* b) {
    asm volatile("mma.sync.aligned.m16n8k16.row.col.f32.f16.f16.f32 "
        "{%0,%1,%2,%3}, {%4,%5,%6,%7}, {%8,%9}, {%0,%1,%2,%3};"
        : "+f"(c[0]), "+f"(c[1]), "+f"(c[2]), "+f"(c[3])
        : "r"(a[0]), "r"(a[1]), "r"(a[2]), "r"(a[3]), "r"(b[0]), "r"(b[1]));
}
__device__ __forceinline__ void cpa16(uint32_t dst, const void* src) {
    asm volatile("cp.async.cg.shared.global [%0], [%1], 16;" :: "r"(dst), "l"(src) : "memory");
}
#define CPA_COMMIT() asm volatile("cp.async.commit_group;" ::: "memory")
#define CPA_WAIT1()  asm volatile("cp.async.wait_group 1;" ::: "memory")

// ---------------- block reduce ----------------------------------------------
__device__ __forceinline__ float blockReduceSum256(float v, float* red) {
    int tid = threadIdx.x;
    #pragma unroll
    for (int o = 16; o; o >>= 1) v += __shfl_down_sync(0xffffffffu, v, o);
    if ((tid & 31) == 0) red[tid >> 5] = v;
    __syncthreads();
    if (tid < 32) {
        float x = (tid < 8) ? red[tid] : 0.f;
        #pragma unroll
        for (int o = 4; o; o >>= 1) x += __shfl_down_sync(0xffffffffu, x, o);
        if (tid == 0) red[0] = x;
    }
    __syncthreads();
    float r = red[0];
    __syncthreads();
    return r;
}

// ---------------- k_cvt: convert ALL weights fp32->half (pad layer1 K) ------
#define CVT_TOTAL 6488064
#define CVT_BLOCKS 3168        // 3168*256*8 == CVT_TOTAL

__global__ void k_cvt(const float* __restrict__ cW1, const float* __restrict__ dW1,
                      const float* __restrict__ cW2, const float* __restrict__ dW2,
                      const float* __restrict__ cW3, const float* __restrict__ dW3)
{
    size_t idx = ((size_t)blockIdx.x * 256 + threadIdx.x) * 8;
    const float* src; __half* dst;
    int KIN, KPAD, N;
    size_t off;
    if      (idx < 557056)  { src = cW1; dst = g_wh1c; KIN = Tt;  KPAD = K1P; N = 512; off = idx; }
    else if (idx < 5013504) { src = dW1; dst = g_wh1d; KIN = Tt;  KPAD = K1P; N = 512; off = idx - 557056; }
    else if (idx < 5144576) { src = cW2; dst = g_wh2c; KIN = 512; KPAD = 512; N = 256; off = idx - 5013504; }
    else if (idx < 6193152) { src = dW2; dst = g_wh2d; KIN = 512; KPAD = 512; N = 256; off = idx - 5144576; }
    else if (idx < 6225920) { src = cW3; dst = g_wh3c; KIN = 256; KPAD = 256; N = 128; off = idx - 6193152; }
    else                    { src = dW3; dst = g_wh3d; KIN = 256; KPAD = 256; N = 128; off = idx - 6225920; }

    size_t per = (size_t)KPAD * N;
    int d = (int)(off / per);
    size_t r = off % per;
    int k = (int)(r / N), n = (int)(r % N);
    uint4 u;
    if (k < KIN) {
        const float* s = src + ((size_t)d * KIN + k) * N + n;
        float4 f0 = *(const float4*)s;
        float4 f1 = *(const float4*)(s + 4);
        __half2 h0 = __floats2half2_rn(f0.x, f0.y), h1 = __floats2half2_rn(f0.z, f0.w);
        __half2 h2 = __floats2half2_rn(f1.x, f1.y), h3 = __floats2half2_rn(f1.z, f1.w);
        u.x = *(uint32_t*)&h0; u.y = *(uint32_t*)&h1;
        u.z = *(uint32_t*)&h2; u.w = *(uint32_t*)&h3;
    } else {
        u = make_uint4(0, 0, 0, 0);
    }
    *(uint4*)(dst + off) = u;
}

// ---------------- partition: counts, offsets, permutation (one block) -------
__global__ void k_part(const int* __restrict__ dom) {
    __shared__ int scnt[Dd], soff[Dd], scur[Dd];
    int t = threadIdx.x;
    if (t < Dd) { scnt[t] = 0; scur[t] = 0; }
    __syncthreads();
    int dv[4];
    #pragma unroll
    for (int i = 0; i < 4; i++) { dv[i] = dom[t + 1024 * i]; atomicAdd(&scnt[dv[i]], 1); }
    __syncthreads();
    if (t == 0) {
        int s = 0;
        for (int d = 0; d < Dd; d++) { soff[d] = s; g_off[d] = s; g_cnt[d] = scnt[d]; s += scnt[d]; }
    }
    __syncthreads();
    #pragma unroll
    for (int i = 0; i < 4; i++) {
        int p = atomicAdd(&scur[dv[i]], 1);
        g_perm[soff[dv[i]] + p] = t + 1024 * i;
    }
}

// ---------------- k_prep: LayerNorm + domain affine + cross net + aux -------
__global__ void k_prep(const float* __restrict__ x, const int* __restrict__ dom,
                       const float* __restrict__ pnw, const float* __restrict__ pnb,
                       const float* __restrict__ demb,
                       const float* __restrict__ cw, const float* __restrict__ cb,
                       const float* __restrict__ aW1, const float* __restrict__ ab1,
                       const float* __restrict__ aW2, const float* __restrict__ ab2)
{
    int r = blockIdx.x;
    int tid = threadIdx.x;
    __shared__ float s_x0[Tt];
    __shared__ float s_xc[Tt];
    __shared__ float red[32];

    const float* xr = x + (size_t)r * Ff;
    float sum = 0.f, sq = 0.f;
    for (int j = tid; j < Ff; j += 256) { float v = xr[j]; sum += v; sq += v * v; }
    float tot  = blockReduceSum256(sum, red);
    float tot2 = blockReduceSum256(sq, red);
    float mean = tot * (1.f / Ff);
    float var  = tot2 * (1.f / Ff) - mean * mean;
    float rstd = rsqrtf(var + 1e-5f);

    int d = dom[r];
    const float* wr = pnw + (size_t)d * Ff;
    const float* br = pnb + (size_t)d * Ff;
    for (int j = tid; j < Ff; j += 256) {
        float nv = (xr[j] - mean) * rstd * wr[j] + br[j];
        s_x0[j] = nv;
        s_xc[j] = nv;
    }
    for (int e = tid; e < Ee; e += 256) {
        float v = demb[d * Ee + e];
        s_x0[Ff + e] = v;
        s_xc[Ff + e] = v;
    }
    __syncthreads();

    for (int i = 0; i < Ll; i++) {
        const float* wi = cw + i * Tt;
        const float* bi = cb + i * Tt;
        float p = 0.f;
        for (int j = tid; j < Tt; j += 256) p += s_xc[j] * wi[j];
        float proj = blockReduceSum256(p, red);
        for (int j = tid; j < Tt; j += 256)
            s_xc[j] = fmaf(s_x0[j], proj, bi[j] + s_xc[j]);
        __syncthreads();
    }

    __half* out = g_xc + (size_t)r * K1P;
    for (int j = tid; j < Tt; j += 256) out[j] = __float2half_rn(s_xc[j]);
    if (tid < K1P - Tt) out[Tt + tid] = __float2half_rn(0.f);

    if (tid < 32) {
        float s = ab1[tid];
        #pragma unroll
        for (int e = 0; e < Ee; e++) s = fmaf(s_x0[Ff + e], aW1[e * 32 + tid], s);
        s = fmaxf(s, 0.f) * aW2[tid];
        #pragma unroll
        for (int o = 16; o; o >>= 1) s += __shfl_down_sync(0xffffffffu, s, o);
        if (tid == 0) g_aux[r] = s + ab2[0];
    }
}

// ---------------- layer-1 GEMM (round-7 config: 8 warps, 64x32 tiles) -------
#define BK     64
#define LDH    72
#define LDB    136
#define ASZ    (128*LDH)
#define BSZ    (BK*LDB)
#define STAGES 3
#define DYNSM  (STAGES*(ASZ+BSZ)*2)   // 107520 bytes

template<int K, int N, bool RELU, int LAYER>
__global__ __launch_bounds__(256, 2)
void gemm_f16(const __half* __restrict__ Ac, const __half* __restrict__ Ad,
              const __half* __restrict__ Wc, const __half* __restrict__ Wd,
              const float* __restrict__ bc, const float* __restrict__ bd,
              __half* __restrict__ Cc, __half* __restrict__ Cd)
{
    extern __shared__ __align__(16) __half tiles[];
    __shared__ int rowA[128], rowC[128];

    const int z  = blockIdx.z;
    const int n0 = blockIdx.x * 128;
    const int m0 = blockIdx.y * 128;

    const __half *A, *W;
    const float* bias;
    __half* C;
    int cnt;
    if (z == 0) { A = Ac; W = Wc; bias = bc; C = Cc; cnt = Bsz; }
    else {
        int d = z - 1;
        cnt = g_cnt[d];
        if (m0 >= cnt) return;
        A = Ad; W = Wd + (size_t)d * K * N; bias = bd + d * N; C = Cd;
    }

    const int tid  = threadIdx.x;
    const int wid  = tid >> 5;
    const int lane = tid & 31;

    if (tid < 128) {
        if (z == 0) { rowA[tid] = m0 + tid; rowC[tid] = m0 + tid; }
        else {
            int off = g_off[z - 1];
            int mm  = min(m0 + tid, cnt - 1);
            int slot = off + mm;
            if (LAYER == 1)      { rowA[tid] = g_perm[slot]; rowC[tid] = slot; }
            else if (LAYER == 2) { rowA[tid] = slot;         rowC[tid] = slot; }
            else                 { rowA[tid] = slot;         rowC[tid] = g_perm[slot]; }
        }
    }
    __syncthreads();

    const __half* aSrc[4];
    const __half* bSrc[4];
    uint32_t aDst[4], bDst[4];
    #pragma unroll
    for (int i = 0; i < 4; i++) {
        int s  = tid + 256 * i;
        int ar = s >> 3, ac8 = (s & 7) * 8;
        aSrc[i] = A + (size_t)rowA[ar] * K + ac8;
        aDst[i] = (uint32_t)(ar * LDH + ac8) * 2;
        int kr = s >> 4, nc8 = (s & 15) * 8;
        bSrc[i] = W + (size_t)kr * N + n0 + nc8;
        bDst[i] = (uint32_t)(kr * LDB + nc8) * 2;
    }

    const uint32_t sbase = smem_u32(tiles);

    const int wm = (wid & 1) * 64;
    const int wn = (wid >> 1) * 32;
    const int gid = lane >> 2, tig = lane & 3;
    const uint32_t aRowOff = (uint32_t)((wm + (lane & 15)) * LDH + ((lane >> 4) * 8)) * 2;
    const uint32_t bAddrOff = (uint32_t)(((lane & 7) + ((lane >> 3) & 1) * 8) * LDB
                                         + wn + (lane >> 4) * 8) * 2;

    float acc[4][4][4];
    #pragma unroll
    for (int mt = 0; mt < 4; mt++)
        #pragma unroll
        for (int nt = 0; nt < 4; nt++)
            #pragma unroll
            for (int i = 0; i < 4; i++) acc[mt][nt][i] = 0.f;

    const int NCH = K / BK;

    auto issue = [&](int c, int st) {
        uint32_t aS = sbase + (uint32_t)(st * ASZ) * 2;
        uint32_t bS = sbase + (uint32_t)(STAGES * ASZ + st * BSZ) * 2;
        int k0 = c * BK;
        #pragma unroll
        for (int i = 0; i < 4; i++) cpa16(aS + aDst[i], aSrc[i] + k0);
        #pragma unroll
        for (int i = 0; i < 4; i++) cpa16(bS + bDst[i], bSrc[i] + (size_t)k0 * N);
    };

    issue(0, 0); CPA_COMMIT();
    issue(1, 1); CPA_COMMIT();

    for (int c = 0; c < NCH; c++) {
        CPA_WAIT1();
        __syncthreads();
        if (c + 2 < NCH) issue(c + 2, (c + 2) % STAGES);
        CPA_COMMIT();

        const int st = c % STAGES;
        const uint32_t aB = sbase + (uint32_t)(st * ASZ) * 2;
        const uint32_t bB = sbase + (uint32_t)(STAGES * ASZ + st * BSZ) * 2;
        #pragma unroll
        for (int kk = 0; kk < BK; kk += 16) {
            uint32_t af[4][4];
            #pragma unroll
            for (int mt = 0; mt < 4; mt++)
                ldsm4(af[mt], aB + aRowOff + (uint32_t)(mt * 16 * LDH + kk) * 2);
            #pragma unroll
            for (int ntp = 0; ntp < 2; ntp++) {
                uint32_t bf[4];
                ldsm4t(bf, bB + bAddrOff + (uint32_t)(kk * LDB + ntp * 16) * 2);
                #pragma unroll
                for (int mt = 0; mt < 4; mt++) {
                    mma_f16(acc[mt][ntp * 2 + 0], af[mt], bf + 0);
                    mma_f16(acc[mt][ntp * 2 + 1], af[mt], bf + 2);
                }
            }
        }
    }
    __syncthreads();

    __half* stage = tiles;
    #pragma unroll
    for (int mt = 0; mt < 4; mt++) {
        #pragma unroll
        for (int nt = 0; nt < 4; nt++) {
            int col = wn + nt * 8 + 2 * tig;
            float bx = bias[n0 + col], by = bias[n0 + col + 1];
            float v0 = acc[mt][nt][0] + bx, v1 = acc[mt][nt][1] + by;
            float v2 = acc[mt][nt][2] + bx, v3 = acc[mt][nt][3] + by;
            if (RELU) {
                v0 = fmaxf(v0, 0.f); v1 = fmaxf(v1, 0.f);
                v2 = fmaxf(v2, 0.f); v3 = fmaxf(v3, 0.f);
            }
            int r0 = wm + mt * 16 + gid;
            *(__half2*)&stage[r0 * 136 + col]       = __floats2half2_rn(v0, v1);
            *(__half2*)&stage[(r0 + 8) * 136 + col] = __floats2half2_rn(v2, v3);
        }
    }
    __syncthreads();
    #pragma unroll
    for (int i = 0; i < 8; i++) {
        int idx = tid + 256 * i;
        int r = idx >> 4, c8 = (idx & 15) * 8;
        if (z == 0 || m0 + r < cnt) {
            uint4 v = *(uint4*)&stage[r * 136 + c8];
            *(uint4*)&C[(size_t)rowC[r] * N + n0 + c8] = v;
        }
    }
}

// ---------------- fused layers 2+3: CTA = 64 rows x N=256, then K=256->128 --
// Phase A: T[64,256] = relu(A[64,512] @ W2 + b2)  (T in smem, half)
// Phase B: C[64,128] = T @ W3 + b3                (W3 preloaded in smem)
#define BK2   32
#define LDH2  40                  // A pitch (halfs)
#define LDB2  264                 // W2 tile pitch (halfs), N=256+8
#define LDT   264                 // T pitch
#define LDW3  136                 // W3 pitch
#define A2SZ  (64*LDH2)           // 2560 halfs per stage
#define B2SZ  (BK2*LDB2)          // 8448 halfs per stage
#define OFF_T   (3*A2SZ + 3*B2SZ)         // 33024
#define OFF_W3  (OFF_T + 64*LDT)          // 49920
#define DYNSM23 ((OFF_W3 + 256*LDW3) * 2) // 169472 bytes

__global__ __launch_bounds__(256)
void gemm23(const __half* __restrict__ Ac, const __half* __restrict__ Ad,
            const __half* __restrict__ W2c, const __half* __restrict__ W2d,
            const float* __restrict__ b2c, const float* __restrict__ b2d,
            const __half* __restrict__ W3c, const __half* __restrict__ W3d,
            const float* __restrict__ b3c, const float* __restrict__ b3d,
            __half* __restrict__ Cc, __half* __restrict__ Cd)
{
    extern __shared__ __align__(16) __half tiles[];
    __shared__ int rowA[64], rowC[64];

    const int z  = blockIdx.z;
    const int m0 = blockIdx.y * 64;

    const __half *A, *W2, *W3;
    const float *b2, *b3;
    __half* C;
    int cnt;
    if (z == 0) { A = Ac; W2 = W2c; b2 = b2c; W3 = W3c; b3 = b3c; C = Cc; cnt = Bsz; }
    else {
        int d = z - 1;
        cnt = g_cnt[d];
        if (m0 >= cnt) return;
        A  = Ad;
        W2 = W2d + (size_t)d * 512 * 256; b2 = b2d + d * 256;
        W3 = W3d + (size_t)d * 256 * 128; b3 = b3d + d * 128;
        C  = Cd;
    }

    const int tid  = threadIdx.x;
    const int wid  = tid >> 5;
    const int lane = tid & 31;

    if (tid < 64) {
        if (z == 0) { rowA[tid] = m0 + tid; rowC[tid] = m0 + tid; }
        else {
            int off = g_off[z - 1];
            int mm  = min(m0 + tid, cnt - 1);
            int slot = off + mm;
            rowA[tid] = slot;             // layer2 reads packed slots
            rowC[tid] = g_perm[slot];     // layer3 scatters to original rows
        }
    }
    __syncthreads();

    const uint32_t sbase = smem_u32(tiles);

    // ---- W3 preload (group 0): 256x128 -> smem pitch 136, 16 slots/thread --
    {
        uint32_t w3S = sbase + (uint32_t)OFF_W3 * 2;
        #pragma unroll
        for (int i = 0; i < 16; i++) {
            int s = tid + 256 * i;
            int kr = s >> 4, nc8 = (s & 15) * 8;
            cpa16(w3S + (uint32_t)(kr * LDW3 + nc8) * 2, W3 + (size_t)kr * 128 + nc8);
        }
        CPA_COMMIT();
    }

    // ---- phase A loaders: A 1 slot, B 4 slots per thread -------------------
    const __half* aSrc = A + (size_t)rowA[tid >> 2] * 512 + (tid & 3) * 8;
    const uint32_t aDst = (uint32_t)((tid >> 2) * LDH2 + (tid & 3) * 8) * 2;
    const __half* bSrc[4];
    uint32_t bDst[4];
    #pragma unroll
    for (int i = 0; i < 4; i++) {
        int s = tid + 256 * i;
        int kr = s >> 5, nc8 = (s & 31) * 8;
        bSrc[i] = W2 + (size_t)kr * 256 + nc8;
        bDst[i] = (uint32_t)(kr * LDB2 + nc8) * 2;
    }

    auto issue = [&](int c, int st) {
        uint32_t aS = sbase + (uint32_t)(st * A2SZ) * 2;
        uint32_t bS = sbase + (uint32_t)(3 * A2SZ + st * B2SZ) * 2;
        int k0 = c * BK2;
        cpa16(aS + aDst, aSrc + k0);
        #pragma unroll
        for (int i = 0; i < 4; i++) cpa16(bS + bDst[i], bSrc[i] + (size_t)k0 * 256);
    };

    issue(0, 0); CPA_COMMIT();
    issue(1, 1); CPA_COMMIT();

    // ---- phase A fragments: 8 warps, warp tile 32(m) x 64(n) ----------------
    const int wm = (wid & 1) * 32;
    const int wn = (wid >> 1) * 64;
    const int gid = lane >> 2, tig = lane & 3;
    const uint32_t aRowOff = (uint32_t)((wm + (lane & 15)) * LDH2 + ((lane >> 4) * 8)) * 2;
    const uint32_t bAddrOff = (uint32_t)(((lane & 7) + ((lane >> 3) & 1) * 8) * LDB2
                                         + wn + (lane >> 4) * 8) * 2;

    float acc[2][8][4];
    #pragma unroll
    for (int mt = 0; mt < 2; mt++)
        #pragma unroll
        for (int nt = 0; nt < 8; nt++)
            #pragma unroll
            for (int i = 0; i < 4; i++) acc[mt][nt][i] = 0.f;

    const int NCH = 512 / BK2;    // 16
    for (int c = 0; c < NCH; c++) {
        CPA_WAIT1();
        __syncthreads();
        if (c + 2 < NCH) issue(c + 2, (c + 2) % 3);
        CPA_COMMIT();

        const int st = c % 3;
        const uint32_t aB = sbase + (uint32_t)(st * A2SZ) * 2;
        const uint32_t bB = sbase + (uint32_t)(3 * A2SZ + st * B2SZ) * 2;
        #pragma unroll
        for (int kk = 0; kk < BK2; kk += 16) {
            uint32_t af[2][4];
            #pragma unroll
            for (int mt = 0; mt < 2; mt++)
                ldsm4(af[mt], aB + aRowOff + (uint32_t)(mt * 16 * LDH2 + kk) * 2);
            #pragma unroll
            for (int ntp = 0; ntp < 4; ntp++) {
                uint32_t bf[4];
                ldsm4t(bf, bB + bAddrOff + (uint32_t)(kk * LDB2 + ntp * 16) * 2);
                #pragma unroll
                for (int mt = 0; mt < 2; mt++) {
                    mma_f16(acc[mt][ntp * 2 + 0], af[mt], bf + 0);
                    mma_f16(acc[mt][ntp * 2 + 1], af[mt], bf + 2);
                }
            }
        }
    }

    // ---- write T = relu(acc + b2) to smem -----------------------------------
    __half* T = tiles + OFF_T;
    #pragma unroll
    for (int mt = 0; mt < 2; mt++) {
        #pragma unroll
        for (int nt = 0; nt < 8; nt++) {
            int col = wn + nt * 8 + 2 * tig;
            float bx = b2[col], by = b2[col + 1];
            float v0 = fmaxf(acc[mt][nt][0] + bx, 0.f), v1 = fmaxf(acc[mt][nt][1] + by, 0.f);
            float v2 = fmaxf(acc[mt][nt][2] + bx, 0.f), v3 = fmaxf(acc[mt][nt][3] + by, 0.f);
            int r0 = wm + mt * 16 + gid;
            *(__half2*)&T[r0 * LDT + col]       = __floats2half2_rn(v0, v1);
            *(__half2*)&T[(r0 + 8) * LDT + col] = __floats2half2_rn(v2, v3);
        }
    }
    __syncthreads();

    // ---- phase B: C64x128 = T(64x256) @ W3(256x128) + b3 --------------------
    const int wm3 = (wid & 1) * 32;
    const int wn3 = (wid >> 1) * 32;
    const uint32_t tBase  = sbase + (uint32_t)OFF_T * 2;
    const uint32_t w3Base = sbase + (uint32_t)OFF_W3 * 2;
    const uint32_t aOff3 = (uint32_t)((wm3 + (lane & 15)) * LDT + ((lane >> 4) * 8)) * 2;
    const uint32_t bOff3 = (uint32_t)(((lane & 7) + ((lane >> 3) & 1) * 8) * LDW3
                                      + wn3 + (lane >> 4) * 8) * 2;

    float a3[2][4][4];
    #pragma unroll
    for (int mt = 0; mt < 2; mt++)
        #pragma unroll
        for (int nt = 0; nt < 4; nt++)
            #pragma unroll
            for (int i = 0; i < 4; i++) a3[mt][nt][i] = 0.f;

    #pragma unroll
    for (int kk = 0; kk < 256; kk += 16) {
        uint32_t af[2][4];
        #pragma unroll
        for (int mt = 0; mt < 2; mt++)
            ldsm4(af[mt], tBase + aOff3 + (uint32_t)(mt * 16 * LDT + kk) * 2);
        #pragma unroll
        for (int ntp = 0; ntp < 2; ntp++) {
            uint32_t bf[4];
            ldsm4t(bf, w3Base + bOff3 + (uint32_t)(kk * LDW3 + ntp * 16) * 2);
            #pragma unroll
            for (int mt = 0; mt < 2; mt++) {
                mma_f16(a3[mt][ntp * 2 + 0], af[mt], bf + 0);
                mma_f16(a3[mt][ntp * 2 + 1], af[mt], bf + 2);
            }
        }
    }
    __syncthreads();

    // ---- epilogue: bias3 (no relu), stage, coalesced scatter-store ----------
    __half* stage = tiles;   // 64 x 136 halfs, well inside the A/B ring region
    #pragma unroll
    for (int mt = 0; mt < 2; mt++) {
        #pragma unroll
        for (int nt = 0; nt < 4; nt++) {
            int col = wn3 + nt * 8 + 2 * tig;
            float bx = b3[col], by = b3[col + 1];
            float v0 = a3[mt][nt][0] + bx, v1 = a3[mt][nt][1] + by;
            float v2 = a3[mt][nt][2] + bx, v3 = a3[mt][nt][3] + by;
            int r0 = wm3 + mt * 16 + gid;
            *(__half2*)&stage[r0 * 136 + col]       = __floats2half2_rn(v0, v1);
            *(__half2*)&stage[(r0 + 8) * 136 + col] = __floats2half2_rn(v2, v3);
        }
    }
    __syncthreads();
    #pragma unroll
    for (int i = 0; i < 4; i++) {
        int idx = tid + 256 * i;            // 0..1023
        int r = idx >> 4, c8 = (idx & 15) * 8;
        if (z == 0 || m0 + r < cnt) {
            uint4 v = *(uint4*)&stage[r * 136 + c8];
            *(uint4*)&C[(size_t)rowC[r] * 128 + c8] = v;
        }
    }
}

// ---------------- K_final: STAR fusion + final MLP + sigmoid ----------------
__global__ void k_final(const float* __restrict__ fW1, const float* __restrict__ fb1,
                        const float* __restrict__ fW2, const float* __restrict__ fb2,
                        float* __restrict__ out)
{
    int r = blockIdx.x;
    int t = threadIdx.x;
    __shared__ float fs[128];
    __shared__ float red[64];
    fs[t] = __half2float(g_hc[r * 128 + t]) * tanhf(__half2float(g_hd[r * 128 + t]));
    __syncthreads();
    if (t < 64) {
        float s = fb1[t];
        #pragma unroll
        for (int j = 0; j < 128; j++) s = fmaf(fs[j], fW1[j * 64 + t], s);
        red[t] = fmaxf(s, 0.f) * fW2[t];
    }
    __syncthreads();
    if (t < 32) {
        float v = red[t] + red[t + 32];
        #pragma unroll
        for (int o = 16; o; o >>= 1) v += __shfl_down_sync(0xffffffffu, v, o);
        if (t == 0) {
            float logit = v + fb2[0] + g_aux[r];
            out[r] = 1.f / (1.f + expf(-logit));
        }
    }
}

// ---------------- launch -----------------------------------------------------
extern "C" void kernel_launch(void* const* d_in, const int* in_sizes, int n_in,
                              void* d_out, int out_size)
{
    const float* x    = (const float*)d_in[0];
    const int*   dom  = (const int*)  d_in[1];
    const float* pnw  = (const float*)d_in[2];
    const float* pnb  = (const float*)d_in[3];
    const float* demb = (const float*)d_in[4];
    const float* cw   = (const float*)d_in[5];
    const float* cb   = (const float*)d_in[6];
    const float* cW1  = (const float*)d_in[7];
    const float* cb1  = (const float*)d_in[8];
    const float* cW2  = (const float*)d_in[9];
    const float* cb2  = (const float*)d_in[10];
    const float* cW3  = (const float*)d_in[11];
    const float* cb3  = (const float*)d_in[12];
    const float* dW1  = (const float*)d_in[13];
    const float* db1  = (const float*)d_in[14];
    const float* dW2  = (const float*)d_in[15];
    const float* db2  = (const float*)d_in[16];
    const float* dW3  = (const float*)d_in[17];
    const float* db3  = (const float*)d_in[18];
    const float* fW1  = (const float*)d_in[19];
    const float* fb1  = (const float*)d_in[20];
    const float* fW2  = (const float*)d_in[21];
    const float* fb2  = (const float*)d_in[22];
    const float* aW1  = (const float*)d_in[23];
    const float* ab1  = (const float*)d_in[24];
    const float* aW2  = (const float*)d_in[25];
    const float* ab2  = (const float*)d_in[26];
    float* out = (float*)d_out;

    __half *xcP, *ch1P, *hcP, *dg1P, *hdP;
    __half *wh1cP, *wh1dP, *wh2cP, *wh2dP, *wh3cP, *wh3dP;
    cudaGetSymbolAddress((void**)&xcP,  g_xc);
    cudaGetSymbolAddress((void**)&ch1P, g_ch1);
    cudaGetSymbolAddress((void**)&hcP,  g_hc);
    cudaGetSymbolAddress((void**)&dg1P, g_dg1);
    cudaGetSymbolAddress((void**)&hdP,  g_hd);
    cudaGetSymbolAddress((void**)&wh1cP, g_wh1c);
    cudaGetSymbolAddress((void**)&wh1dP, g_wh1d);
    cudaGetSymbolAddress((void**)&wh2cP, g_wh2c);
    cudaGetSymbolAddress((void**)&wh2dP, g_wh2d);
    cudaGetSymbolAddress((void**)&wh3cP, g_wh3c);
    cudaGetSymbolAddress((void**)&wh3dP, g_wh3d);

    cudaFuncSetAttribute(gemm_f16<K1P, 512, true, 1>, cudaFuncAttributeMaxDynamicSharedMemorySize, DYNSM);
    cudaFuncSetAttribute(gemm23, cudaFuncAttributeMaxDynamicSharedMemorySize, DYNSM23);

    k_cvt<<<CVT_BLOCKS, 256>>>(cW1, dW1, cW2, dW2, cW3, dW3);
    k_part<<<1, 1024>>>(dom);
    k_prep<<<Bsz, 256>>>(x, dom, pnw, pnb, demb, cw, cb, aW1, ab1, aW2, ab2);

    // layer 1: K=1088(padded) -> N=512 ; z=0 center, z=1..8 domains
    gemm_f16<K1P, 512, true, 1><<<dim3(4, 32, 9), 256, DYNSM>>>(xcP, xcP, wh1cP, wh1dP, cb1, db1, ch1P, dg1P);
    // fused layers 2+3
    gemm23<<<dim3(1, 64, 9), 256, DYNSM23>>>(ch1P, dg1P, wh2cP, wh2dP, cb2, db2,
                                             wh3cP, wh3dP, cb3, db3, hcP, hdP);

    k_final<<<Bsz, 128>>>(fW1, fb1, fW2, fb2, out);
}